// round 2
// baseline (speedup 1.0000x reference)
#include <cuda_runtime.h>
#include <cstdint>

#define NUM_CLASSES 19
#define C_DIM 256
#define HW 16384
#define BS 8
#define Q_DIM 2975
#define INV_T 5.0f
#define LOG2E 1.4426950408889634f

// scratch (allocation-free: __device__ globals)
__device__ float g_sums[NUM_CLASSES * C_DIM];
__device__ int   g_counts[NUM_CLASSES];
__device__ float g_keys[NUM_CLASSES * C_DIM];
__device__ float g_sumexp[NUM_CLASSES * C_DIM];
__device__ __align__(16) unsigned char g_pred[BS * HW];

// ---------------------------------------------------------------------------
// 0) zero the accumulators (graph replays must be deterministic)
// ---------------------------------------------------------------------------
__global__ void k_init() {
    int i = threadIdx.x;
    for (int j = i; j < NUM_CLASSES * C_DIM; j += 256) g_sums[j] = 0.f;
    if (i < NUM_CLASSES) g_counts[i] = 0;
}

// ---------------------------------------------------------------------------
// 1) argmax over classes per pixel + copy res -> out + class counts
//    res: [BS, 19, HW]; one thread per pixel; loads coalesced per k-slice.
// ---------------------------------------------------------------------------
__global__ void __launch_bounds__(256) k_argmax(const float* __restrict__ res,
                                                float* __restrict__ out,
                                                int do_copy) {
    __shared__ int scnt[NUM_CLASSES];
    int tid = threadIdx.x;
    if (tid < NUM_CLASSES) scnt[tid] = 0;
    __syncthreads();

    int pg = blockIdx.x * 256 + tid;          // 0 .. BS*HW-1
    int b  = pg >> 14;
    int p  = pg & (HW - 1);
    int base = b * NUM_CLASSES * HW + p;

    float best = res[base];
    if (do_copy) out[base] = best;
    int bk = 0;
#pragma unroll
    for (int k = 1; k < NUM_CLASSES; k++) {
        float v = res[base + k * HW];
        if (do_copy) out[base + k * HW] = v;
        if (v > best) { best = v; bk = k; }   // strict > keeps first max (jnp.argmax)
    }
    g_pred[pg] = (unsigned char)bk;
    atomicAdd(&scnt[bk], 1);
    __syncthreads();
    if (tid < NUM_CLASSES) atomicAdd(&g_counts[tid], scnt[tid]);
}

// ---------------------------------------------------------------------------
// 2) masked per-class pooling: sums[k][c] += fea[b,c,p] where pred[b,p]==k
//    block = (c, b); 256 threads sweep pixels; per-thread smem accumulators
//    acc[k*256+tid] -> bank = tid%32, always conflict-free.
// ---------------------------------------------------------------------------
__global__ void __launch_bounds__(256) k_pool(const float* __restrict__ fea) {
    __shared__ float acc[NUM_CLASSES * 256];   // 19 KB
    __shared__ uint4 spred4[HW / 16];          // 16 KB: pred[b] bytes
    int tid = threadIdx.x;
    int c = blockIdx.x, b = blockIdx.y;

#pragma unroll
    for (int k = 0; k < NUM_CLASSES; k++) acc[k * 256 + tid] = 0.f;

    const uint4* pg4 = (const uint4*)(g_pred + b * HW);
    for (int i = tid; i < HW / 16; i += 256) spred4[i] = pg4[i];
    __syncthreads();

    const float4* f4 = (const float4*)(fea + ((b * C_DIM + c) << 14));
    const uchar4* sp = (const uchar4*)spred4;
    for (int i = tid; i < HW / 4; i += 256) {
        float4 v = f4[i];
        uchar4 cl = sp[i];
        acc[cl.x * 256 + tid] += v.x;
        acc[cl.y * 256 + tid] += v.y;
        acc[cl.z * 256 + tid] += v.z;
        acc[cl.w * 256 + tid] += v.w;
    }
    __syncthreads();

    for (int s = 128; s > 0; s >>= 1) {
        if (tid < s) {
#pragma unroll
            for (int k = 0; k < NUM_CLASSES; k++)
                acc[k * 256 + tid] += acc[k * 256 + tid + s];
        }
        __syncthreads();
    }
    if (tid < NUM_CLASSES) atomicAdd(&g_sums[tid * C_DIM + c], acc[tid * 256]);
}

// ---------------------------------------------------------------------------
// 3) keys = normalize(sums / max(count,1)) along C
// ---------------------------------------------------------------------------
__global__ void __launch_bounds__(256) k_keys() {
    __shared__ float swarp[8];
    __shared__ float snorm;
    int tid = threadIdx.x, lane = tid & 31, w = tid >> 5;
    for (int k = 0; k < NUM_CLASSES; k++) {
        float cnt = fmaxf((float)g_counts[k], 1.0f);
        float v = g_sums[k * 256 + tid] / cnt;
        float sq = v * v;
#pragma unroll
        for (int o = 16; o; o >>= 1) sq += __shfl_down_sync(0xffffffffu, sq, o);
        if (lane == 0) swarp[w] = sq;
        __syncthreads();
        if (tid == 0) {
            float s = 0.f;
#pragma unroll
            for (int i = 0; i < 8; i++) s += swarp[i];
            snorm = fmaxf(sqrtf(s), 1e-12f);
        }
        __syncthreads();
        g_keys[k * 256 + tid] = v / snorm;
        __syncthreads();
    }
}

// ---------------------------------------------------------------------------
// 4) fused qsum + logits + sum-of-exp.  One block per channel c.
//    Each thread handles q-slices; reads u_k = queues[k,c,q] for all 19 k,
//    s = sum_k u_k (= qsum[c,q]), then
//      l_pos = a_k*u_k, l_neg = a_k*s - a_k*u_k  (a_k = keys[k,c]*log2e/T)
//    accumulates S[k,c] = sum_q exp2(l_pos)+exp2(l_neg) = sum exp(logits).
//    Single pass over queues (58 MB).
// ---------------------------------------------------------------------------
__global__ void __launch_bounds__(256) k_lse(const float* __restrict__ queues) {
    int tid = threadIdx.x, c = blockIdx.x;
    int lane = tid & 31, w = tid >> 5;

    float a[NUM_CLASSES];
#pragma unroll
    for (int k = 0; k < NUM_CLASSES; k++)
        a[k] = g_keys[k * 256 + c] * (INV_T * LOG2E);

    float acc[NUM_CLASSES];
#pragma unroll
    for (int k = 0; k < NUM_CLASSES; k++) acc[k] = 0.f;

    const float* qc = queues + c * Q_DIM;
    const int kstride = C_DIM * Q_DIM;
    for (int q = tid; q < Q_DIM; q += 256) {
        float u[NUM_CLASSES];
        float s = 0.f;
#pragma unroll
        for (int k = 0; k < NUM_CLASSES; k++) { u[k] = qc[k * kstride + q]; s += u[k]; }
#pragma unroll
        for (int k = 0; k < NUM_CLASSES; k++) {
            float v1 = a[k] * u[k];
            float v2 = a[k] * s - v1;
            float e1, e2;
            asm("ex2.approx.f32 %0, %1;" : "=f"(e1) : "f"(v1));
            asm("ex2.approx.f32 %0, %1;" : "=f"(e2) : "f"(v2));
            acc[k] += e1 + e2;
        }
    }

#pragma unroll
    for (int k = 0; k < NUM_CLASSES; k++)
#pragma unroll
        for (int o = 16; o; o >>= 1) acc[k] += __shfl_down_sync(0xffffffffu, acc[k], o);

    __shared__ float red[NUM_CLASSES][8];
    if (lane == 0) {
#pragma unroll
        for (int k = 0; k < NUM_CLASSES; k++) red[k][w] = acc[k];
    }
    __syncthreads();
    if (tid < NUM_CLASSES) {
        float s = 0.f;
#pragma unroll
        for (int i = 0; i < 8; i++) s += red[tid][i];
        g_sumexp[tid * 256 + c] = s;
    }
}

// ---------------------------------------------------------------------------
// 5) loss = (1/C) * sum over present classes, channels of (ln S - keys*q0/T)
// ---------------------------------------------------------------------------
__global__ void __launch_bounds__(256) k_loss(const float* __restrict__ queues,
                                              float* __restrict__ out, int loss_idx) {
    int tid = threadIdx.x;        // channel c
    float tot = 0.f;
    for (int k = 0; k < NUM_CLASSES; k++) {
        if (g_counts[k] > 0) {
            int idx = k * 256 + tid;
            float q0 = queues[idx * Q_DIM];   // queues[k,c,0]
            tot += logf(g_sumexp[idx]) - g_keys[idx] * q0 * INV_T;
        }
    }
    int lane = tid & 31, w = tid >> 5;
#pragma unroll
    for (int o = 16; o; o >>= 1) tot += __shfl_down_sync(0xffffffffu, tot, o);
    __shared__ float red[8];
    if (lane == 0) red[w] = tot;
    __syncthreads();
    if (tid == 0) {
        float s = 0.f;
#pragma unroll
        for (int i = 0; i < 8; i++) s += red[i];
        out[loss_idx] = s * (1.0f / (float)C_DIM);
    }
}

// ---------------------------------------------------------------------------
extern "C" void kernel_launch(void* const* d_in, const int* in_sizes, int n_in,
                              void* d_out, int out_size) {
    const float* fea    = (const float*)d_in[0];
    const float* res    = (const float*)d_in[1];
    const float* queues = (const float*)d_in[2];
    float* out = (float*)d_out;

    const int res_elems = BS * NUM_CLASSES * HW;
    int do_copy = (out_size > res_elems) ? 1 : 0;
    int loss_idx = (out_size > 0) ? (out_size - 1) : 0;

    k_init<<<1, 256>>>();
    k_argmax<<<(BS * HW) / 256, 256>>>(res, out, do_copy);
    k_pool<<<dim3(C_DIM, BS), 256>>>(fea);
    k_keys<<<1, 256>>>();
    k_lse<<<C_DIM, 256>>>(queues);
    k_loss<<<1, 256>>>(queues, out, loss_idx);
}

// round 4
// speedup vs baseline: 1.3714x; 1.3714x over previous
#include <cuda_runtime.h>
#include <cstdint>

#define NUM_CLASSES 19
#define C_DIM 256
#define HW 16384
#define BS 8
#define Q_DIM 2975
#define QCH 744            // ceil(2975/4), q-chunk per lse block
#define INV_T 5.0f
#define LOG2E 1.4426950408889634f

// scratch (allocation-free: __device__ globals)
__device__ float g_sums[NUM_CLASSES * C_DIM];
__device__ int   g_counts[NUM_CLASSES];
__device__ float g_keys[NUM_CLASSES * C_DIM];
__device__ float g_sumexp[NUM_CLASSES * C_DIM];
__device__ __align__(16) unsigned char g_pred[BS * HW];

// ---------------------------------------------------------------------------
// 0) zero the accumulators (graph replays must be deterministic)
// ---------------------------------------------------------------------------
__global__ void k_init() {
    int i = threadIdx.x;
    for (int j = i; j < NUM_CLASSES * C_DIM; j += 256) {
        g_sums[j] = 0.f;
        g_sumexp[j] = 0.f;
    }
    if (i < NUM_CLASSES) g_counts[i] = 0;
}

// ---------------------------------------------------------------------------
// 1) argmax over classes per pixel + copy res -> out + class counts
// ---------------------------------------------------------------------------
__global__ void __launch_bounds__(256) k_argmax(const float* __restrict__ res,
                                                float* __restrict__ out,
                                                int do_copy) {
    __shared__ int scnt[NUM_CLASSES];
    int tid = threadIdx.x;
    if (tid < NUM_CLASSES) scnt[tid] = 0;
    __syncthreads();

    int pg = blockIdx.x * 256 + tid;          // 0 .. BS*HW-1
    int b  = pg >> 14;
    int p  = pg & (HW - 1);
    int base = b * NUM_CLASSES * HW + p;

    float best = res[base];
    if (do_copy) out[base] = best;
    int bk = 0;
#pragma unroll
    for (int k = 1; k < NUM_CLASSES; k++) {
        float v = res[base + k * HW];
        if (do_copy) out[base + k * HW] = v;
        if (v > best) { best = v; bk = k; }   // strict > keeps first max (jnp.argmax)
    }
    g_pred[pg] = (unsigned char)bk;
    atomicAdd(&scnt[bk], 1);
    __syncthreads();
    if (tid < NUM_CLASSES) atomicAdd(&g_counts[tid], scnt[tid]);
}

// ---------------------------------------------------------------------------
// 2) masked per-class pooling: sums[k][c] += fea[b,c,p] where pred[b,p]==k
//    block=(c,b); pred read straight from L2 (128KB resident, reused 256x);
//    per-thread smem accumulators acc[k*256+tid] -> bank=tid%32, conflict-free.
// ---------------------------------------------------------------------------
__global__ void __launch_bounds__(256) k_pool(const float* __restrict__ fea) {
    __shared__ float acc[NUM_CLASSES * 256];   // 19 KB
    int tid = threadIdx.x;
    int c = blockIdx.x, b = blockIdx.y;

#pragma unroll
    for (int k = 0; k < NUM_CLASSES; k++) acc[k * 256 + tid] = 0.f;
    __syncthreads();

    const float4* f4 = (const float4*)(fea + ((b * C_DIM + c) << 14));
    const uchar4* sp = (const uchar4*)(g_pred + b * HW);
#pragma unroll 4
    for (int i = tid; i < HW / 4; i += 256) {
        float4 v = f4[i];
        uchar4 cl = __ldg(sp + i);
        acc[cl.x * 256 + tid] += v.x;
        acc[cl.y * 256 + tid] += v.y;
        acc[cl.z * 256 + tid] += v.z;
        acc[cl.w * 256 + tid] += v.w;
    }
    __syncthreads();

    for (int s = 128; s > 0; s >>= 1) {
        if (tid < s) {
#pragma unroll
            for (int k = 0; k < NUM_CLASSES; k++)
                acc[k * 256 + tid] += acc[k * 256 + tid + s];
        }
        __syncthreads();
    }
    if (tid < NUM_CLASSES) atomicAdd(&g_sums[tid * C_DIM + c], acc[tid * 256]);
}

// ---------------------------------------------------------------------------
// 3) keys = normalize(sums / max(count,1)) along C.
//    One warp per class (grid=19, block=32). No barriers, no serial chain.
// ---------------------------------------------------------------------------
__global__ void __launch_bounds__(32) k_keys() {
    int k = blockIdx.x, lane = threadIdx.x;
    float cnt = fmaxf((float)g_counts[k], 1.0f);
    float inv_cnt = 1.0f / cnt;
    float v[8];
    float sq = 0.f;
#pragma unroll
    for (int i = 0; i < 8; i++) {
        v[i] = g_sums[k * 256 + i * 32 + lane] * inv_cnt;
        sq += v[i] * v[i];
    }
#pragma unroll
    for (int o = 16; o; o >>= 1) sq += __shfl_xor_sync(0xffffffffu, sq, o);
    float inv_norm = 1.0f / fmaxf(sqrtf(sq), 1e-12f);
#pragma unroll
    for (int i = 0; i < 8; i++)
        g_keys[k * 256 + i * 32 + lane] = v[i] * inv_norm;
}

// ---------------------------------------------------------------------------
// 4) fused qsum + logits + sum-of-exp.  Block=(c, qchunk of 4).
//    u_k = queues[k,c,q], s = sum_k u_k (= qsum[c,q]);
//    S[k,c] += sum_q exp2(a_k*u_k) + exp2(a_k*(s-u_k)),  a_k=keys[k,c]*log2e/T.
//    Single pass over queues (58 MB), partials via atomicAdd.
// ---------------------------------------------------------------------------
__global__ void __launch_bounds__(256) k_lse(const float* __restrict__ queues) {
    int tid = threadIdx.x, c = blockIdx.x, j = blockIdx.y;
    int lane = tid & 31, w = tid >> 5;
    int q0 = j * QCH;
    int q1 = min(q0 + QCH, Q_DIM);

    float a[NUM_CLASSES];
#pragma unroll
    for (int k = 0; k < NUM_CLASSES; k++)
        a[k] = g_keys[k * 256 + c] * (INV_T * LOG2E);

    float acc[NUM_CLASSES];
#pragma unroll
    for (int k = 0; k < NUM_CLASSES; k++) acc[k] = 0.f;

    const float* qc = queues + c * Q_DIM;
    const int kstride = C_DIM * Q_DIM;
    for (int q = q0 + tid; q < q1; q += 256) {
        float u[NUM_CLASSES];
        float s = 0.f;
#pragma unroll
        for (int k = 0; k < NUM_CLASSES; k++) { u[k] = __ldg(qc + k * kstride + q); s += u[k]; }
#pragma unroll
        for (int k = 0; k < NUM_CLASSES; k++) {
            float v1 = a[k] * u[k];
            float v2 = a[k] * s - v1;
            float e1, e2;
            asm("ex2.approx.f32 %0, %1;" : "=f"(e1) : "f"(v1));
            asm("ex2.approx.f32 %0, %1;" : "=f"(e2) : "f"(v2));
            acc[k] += e1 + e2;
        }
    }

#pragma unroll
    for (int k = 0; k < NUM_CLASSES; k++)
#pragma unroll
        for (int o = 16; o; o >>= 1) acc[k] += __shfl_down_sync(0xffffffffu, acc[k], o);

    __shared__ float red[NUM_CLASSES][8];
    if (lane == 0) {
#pragma unroll
        for (int k = 0; k < NUM_CLASSES; k++) red[k][w] = acc[k];
    }
    __syncthreads();
    if (tid < NUM_CLASSES) {
        float s = 0.f;
#pragma unroll
        for (int i = 0; i < 8; i++) s += red[tid][i];
        atomicAdd(&g_sumexp[tid * 256 + c], s);
    }
}

// ---------------------------------------------------------------------------
// 5) loss = (1/C) * sum over present classes, channels of (ln S - keys*q0/T)
// ---------------------------------------------------------------------------
__global__ void __launch_bounds__(256) k_loss(const float* __restrict__ queues,
                                              float* __restrict__ out, int loss_idx) {
    int tid = threadIdx.x;        // channel c
    float tot = 0.f;
    for (int k = 0; k < NUM_CLASSES; k++) {
        if (g_counts[k] > 0) {
            int idx = k * 256 + tid;
            float q0 = __ldg(queues + (size_t)idx * Q_DIM);   // queues[k,c,0]
            tot += logf(g_sumexp[idx]) - g_keys[idx] * q0 * INV_T;
        }
    }
    int lane = tid & 31, w = tid >> 5;
#pragma unroll
    for (int o = 16; o; o >>= 1) tot += __shfl_down_sync(0xffffffffu, tot, o);
    __shared__ float red[8];
    if (lane == 0) red[w] = tot;
    __syncthreads();
    if (tid == 0) {
        float s = 0.f;
#pragma unroll
        for (int i = 0; i < 8; i++) s += red[i];
        out[loss_idx] = s * (1.0f / (float)C_DIM);
    }
}

// ---------------------------------------------------------------------------
extern "C" void kernel_launch(void* const* d_in, const int* in_sizes, int n_in,
                              void* d_out, int out_size) {
    const float* fea    = (const float*)d_in[0];
    const float* res    = (const float*)d_in[1];
    const float* queues = (const float*)d_in[2];
    float* out = (float*)d_out;

    const int res_elems = BS * NUM_CLASSES * HW;
    int do_copy = (out_size > res_elems) ? 1 : 0;
    int loss_idx = (out_size > 0) ? (out_size - 1) : 0;

    k_init<<<1, 256>>>();
    k_argmax<<<(BS * HW) / 256, 256>>>(res, out, do_copy);
    k_pool<<<dim3(C_DIM, BS), 256>>>(fea);
    k_keys<<<NUM_CLASSES, 32>>>();
    k_lse<<<dim3(C_DIM, 4), 256>>>(queues);
    k_loss<<<1, 256>>>(queues, out, loss_idx);
}